// round 16
// baseline (speedup 1.0000x reference)
#include <cuda_runtime.h>
#include <cuda_fp16.h>
#include <cstdint>

#define BATCH 8
#define CCH   256
#define NPIX  4096
#define TQ    64
#define TK    64
#define NQT   (NPIX/TQ)
#define NCTA_ATTN (BATCH*NQT)

__device__ __align__(16) float g_proj[(size_t)BATCH*64*NPIX];   // rows 0-31 q, 32-63 k (fp32)
__device__ __align__(16) __half g_vh[(size_t)BATCH*CCH*NPIX];   // V in fp16
__device__ __align__(16) uint32_t g_qkh[(size_t)BATCH*32*NPIX]; // fp16x2 hi: planes 0-15 Q, 16-31 K
__device__ __align__(16) uint32_t g_qkl[(size_t)BATCH*32*NPIX]; // fp16x2 lo
__device__ __align__(16) float g_y[(size_t)BATCH*CCH*NPIX];
__device__ __align__(16) float g_psum[NCTA_ATTN*CCH];
__device__ __align__(16) float g_psq[NCTA_ATTN*CCH];
__device__ __align__(16) float g_bn[2*CCH];

__device__ __forceinline__ uint32_t f2tf(float f){
    uint32_t r; asm("cvt.rna.tf32.f32 %0, %1;" : "=r"(r) : "f"(f)); return r;
}
__device__ __forceinline__ uint32_t f16pack(float lo, float hi){
    uint32_t r; asm("cvt.rn.f16x2.f32 %0, %1, %2;" : "=r"(r) : "f"(hi), "f"(lo)); return r;
}
__device__ __forceinline__ void mma_tf32(float* d, const uint32_t* a, uint32_t b0, uint32_t b1){
    asm("mma.sync.aligned.m16n8k8.row.col.f32.tf32.tf32.f32 "
        "{%0,%1,%2,%3},{%4,%5,%6,%7},{%8,%9},{%0,%1,%2,%3};"
        : "+f"(d[0]), "+f"(d[1]), "+f"(d[2]), "+f"(d[3])
        : "r"(a[0]), "r"(a[1]), "r"(a[2]), "r"(a[3]), "r"(b0), "r"(b1));
}
__device__ __forceinline__ void mma_f16(float* d, const uint32_t* a, uint32_t b0, uint32_t b1){
    asm("mma.sync.aligned.m16n8k16.row.col.f32.f16.f16.f32 "
        "{%0,%1,%2,%3},{%4,%5,%6,%7},{%8,%9},{%0,%1,%2,%3};"
        : "+f"(d[0]), "+f"(d[1]), "+f"(d[2]), "+f"(d[3])
        : "r"(a[0]), "r"(a[1]), "r"(a[2]), "r"(a[3]), "r"(b0), "r"(b1));
}

// ---------------- Kernel A: projection GEMM on tensor cores ----------------
__global__ __launch_bounds__(256) void projmma_kernel(
    const float* __restrict__ x,
    const float* __restrict__ wq, const float* __restrict__ bq,
    const float* __restrict__ wk, const float* __restrict__ bk,
    const float* __restrict__ wv, const float* __restrict__ bv)
{
    __shared__ float Ws[64*36];
    __shared__ float Xs[32*136];
    const int t  = threadIdx.x;
    const int w  = t >> 5, l = t & 31;
    const int g  = l >> 2, tig = l & 3;
    const int wm = w & 1, wn = w >> 1;
    const int m0 = wm*32, nw0 = wn*32;
    const int n0 = blockIdx.x*128;
    const int rowbase = blockIdx.y*64;
    const int b  = blockIdx.z;
    const bool is_qk = (blockIdx.y == 0);
    const float* xb = x + (size_t)b*CCH*NPIX;

    float acc[2][4][4];
    #pragma unroll
    for (int mt=0;mt<2;mt++)
        #pragma unroll
        for (int nt=0;nt<4;nt++)
            #pragma unroll
            for (int q=0;q<4;q++) acc[mt][nt][q] = 0.f;

    for (int k0=0; k0<CCH; k0+=32){
        __syncthreads();
        #pragma unroll
        for (int it=0; it<8; it++){
            int e = it*256 + t;
            int r = e >> 5, kk = e & 31;
            int grow = rowbase + r;
            const float* ws; int lr;
            if (grow < 32)      { ws = wq; lr = grow; }
            else if (grow < 64) { ws = wk; lr = grow-32; }
            else                { ws = wv; lr = grow-64; }
            Ws[r*36 + kk] = ws[(size_t)lr*CCH + k0 + kk];
        }
        #pragma unroll
        for (int it=0; it<4; it++){
            int e = it*256 + t;
            int kk = e >> 5, c4 = (e & 31)*4;
            *(float4*)&Xs[kk*136 + c4] = *(const float4*)(xb + (size_t)(k0+kk)*NPIX + n0 + c4);
        }
        __syncthreads();
        #pragma unroll
        for (int ks=0; ks<4; ks++){
            int k8 = ks*8;
            uint32_t ah[2][4], al[2][4];
            #pragma unroll
            for (int mt=0;mt<2;mt++){
                int rb = m0 + mt*16;
                float a0 = Ws[(rb+g  )*36 + k8+tig];
                float a1 = Ws[(rb+g+8)*36 + k8+tig];
                float a2 = Ws[(rb+g  )*36 + k8+tig+4];
                float a3 = Ws[(rb+g+8)*36 + k8+tig+4];
                ah[mt][0]=f2tf(a0); ah[mt][1]=f2tf(a1); ah[mt][2]=f2tf(a2); ah[mt][3]=f2tf(a3);
                if (is_qk){
                    al[mt][0]=f2tf(a0-__uint_as_float(ah[mt][0]));
                    al[mt][1]=f2tf(a1-__uint_as_float(ah[mt][1]));
                    al[mt][2]=f2tf(a2-__uint_as_float(ah[mt][2]));
                    al[mt][3]=f2tf(a3-__uint_as_float(ah[mt][3]));
                }
            }
            uint32_t bh[4][2], bl[4][2];
            #pragma unroll
            for (int nt=0;nt<4;nt++){
                int jn = nw0 + nt*8 + g;
                float b0 = Xs[(k8+tig  )*136 + jn];
                float b1 = Xs[(k8+tig+4)*136 + jn];
                bh[nt][0]=f2tf(b0); bh[nt][1]=f2tf(b1);
                if (is_qk){
                    bl[nt][0]=f2tf(b0-__uint_as_float(bh[nt][0]));
                    bl[nt][1]=f2tf(b1-__uint_as_float(bh[nt][1]));
                }
            }
            #pragma unroll
            for (int mt=0;mt<2;mt++)
                #pragma unroll
                for (int nt=0;nt<4;nt++){
                    mma_tf32(acc[mt][nt], ah[mt], bh[nt][0], bh[nt][1]);
                    if (is_qk){
                        mma_tf32(acc[mt][nt], al[mt], bh[nt][0], bh[nt][1]);
                        mma_tf32(acc[mt][nt], ah[mt], bl[nt][0], bl[nt][1]);
                    }
                }
        }
    }
    #pragma unroll
    for (int mt=0;mt<2;mt++){
        #pragma unroll
        for (int h=0;h<2;h++){
            int lrow = m0 + mt*16 + g + h*8;
            int grow = rowbase + lrow;
            float bias;
            if (grow < 32)      bias = bq[grow];
            else if (grow < 64) bias = bk[grow-32];
            else                bias = bv[grow-64];
            #pragma unroll
            for (int nt=0;nt<4;nt++){
                int pix = n0 + nw0 + nt*8 + 2*tig;
                float v0 = acc[mt][nt][h*2+0] + bias;
                float v1 = acc[mt][nt][h*2+1] + bias;
                if (is_qk){
                    *(float2*)(g_proj + ((size_t)b*64 + grow)*NPIX + pix) = make_float2(v0, v1);
                } else {
                    *(uint32_t*)&g_vh[((size_t)b*CCH + (grow-64))*NPIX + pix] = f16pack(v0, v1);
                }
            }
        }
    }
}

// ---------------- Kernel A2: pack Q/K into fp16 hi/lo planes ---------------
// plane p (0..31): rows 2p, 2p+1 of g_proj -> fp16x2 (d, d+1) per pixel.
__global__ __launch_bounds__(256) void qkpack_kernel()
{
    int e = blockIdx.x*256 + threadIdx.x;     // uint4 output index
    int pix = (e & 1023) * 4;                 // 4096/4 pairs per plane
    int plane = (e >> 10) & 31;
    int b = e >> 15;
    const float* r0 = g_proj + ((size_t)b*64 + 2*plane)*NPIX + pix;
    const float* r1 = r0 + NPIX;
    float4 v0 = *(const float4*)r0;
    float4 v1 = *(const float4*)r1;
    uint4 hp, lp;
    float a0, a1;
    a0 = v0.x; a1 = v1.x;
    { __half h0=__float2half_rn(a0), h1=__float2half_rn(a1);
      hp.x = f16pack(a0, a1) ; hp.x = ((*(uint16_t*)&h1)<<16)|(*(uint16_t*)&h0);
      lp.x = f16pack(a0-__half2float(h0), a1-__half2float(h1)); }
    a0 = v0.y; a1 = v1.y;
    { __half h0=__float2half_rn(a0), h1=__float2half_rn(a1);
      hp.y = ((*(uint16_t*)&h1)<<16)|(*(uint16_t*)&h0);
      lp.y = f16pack(a0-__half2float(h0), a1-__half2float(h1)); }
    a0 = v0.z; a1 = v1.z;
    { __half h0=__float2half_rn(a0), h1=__float2half_rn(a1);
      hp.z = ((*(uint16_t*)&h1)<<16)|(*(uint16_t*)&h0);
      lp.z = f16pack(a0-__half2float(h0), a1-__half2float(h1)); }
    a0 = v0.w; a1 = v1.w;
    { __half h0=__float2half_rn(a0), h1=__float2half_rn(a1);
      hp.w = ((*(uint16_t*)&h1)<<16)|(*(uint16_t*)&h0);
      lp.w = f16pack(a0-__half2float(h0), a1-__half2float(h1)); }
    *(uint4*)&g_qkh[((size_t)b*32 + plane)*NPIX + pix] = hp;
    *(uint4*)&g_qkl[((size_t)b*32 + plane)*NPIX + pix] = lp;
}

// ---------------- Kernel B: flash attention -------------------------------
// QK: fp16-split (hi/lo, 3 chains of m16n8k16).  PV: fp16 m16n8k16.
// Staging is now pure uint32 copies from pre-packed g_qkh/g_qkl.
#define VSTR 72
#define QKS  20
__global__ __launch_bounds__(256,2) void attn_kernel(
    const float* __restrict__ x, const float* __restrict__ gamma)
{
    extern __shared__ char smraw[];
    __half* Vb = (__half*)smraw;                     // [256][72] fp16
    __half* Pb = Vb + 256*VSTR;                      // [64][72] fp16
    uint32_t* Qh32 = (uint32_t*)(Pb + 64*VSTR);      // [64][20]
    uint32_t* Ql32 = Qh32 + 64*QKS;
    uint32_t* Kh32 = Ql32 + 64*QKS;
    uint32_t* Kl32 = Kh32 + 64*QKS;
    float* pmax2 = (float*)(Kl32 + 64*QKS);
    float* psum2 = pmax2 + 128;
    float* row_m = psum2 + 128;
    float* row_l = row_m + 64;
    float* row_sc= row_l + 64;
    float* row_rl= row_sc + 64;

    const int t  = threadIdx.x;
    const int w  = t >> 5, l = t & 31;
    const int g  = l >> 2, tig = l & 3;
    const int b  = blockIdx.y;
    const int i0 = blockIdx.x * TQ;
    const uint32_t* qh = g_qkh + (size_t)b*32*NPIX;
    const uint32_t* ql = g_qkl + (size_t)b*32*NPIX;
    const uint32_t* kh = qh + (size_t)16*NPIX;
    const uint32_t* kl = ql + (size_t)16*NPIX;
    const __half* vhg = g_vh + (size_t)b*CCH*NPIX;

    // stage Q once: pure copies
    #pragma unroll
    for (int it=0; it<4; it++){
        int p = it*256 + t;
        int i = p & 63, dp = p >> 6;
        Qh32[i*QKS + dp] = qh[(size_t)dp*NPIX + i0 + i];
        Ql32[i*QKS + dp] = ql[(size_t)dp*NPIX + i0 + i];
    }
    if (t < 64){ row_m[t] = -1e30f; row_l[t] = 0.f; }

    const int wb = w & 3, wc = w >> 2;
    const int m0 = wb*16, nqk0 = wc*32;
    const int c0 = w*32;

    float d_acc[2][8][4];
    #pragma unroll
    for (int mt=0;mt<2;mt++)
        #pragma unroll
        for (int nt=0;nt<8;nt++)
            #pragma unroll
            for (int q=0;q<4;q++) d_acc[mt][nt][q] = 0.f;

    for (int j0=0; j0<NPIX; j0+=TK){
        __syncthreads();
        // stage K: pure copies
        #pragma unroll
        for (int it=0; it<4; it++){
            int p = it*256 + t;
            int j = p & 63, dp = p >> 6;
            Kh32[j*QKS + dp] = kh[(size_t)dp*NPIX + j0 + j];
            Kl32[j*QKS + dp] = kl[(size_t)dp*NPIX + j0 + j];
        }
        // stage V fp16: [256 c][72]
        #pragma unroll
        for (int it=0; it<8; it++){
            int e = it*256 + t;
            int c = e >> 3, q = e & 7;
            *(uint4*)&Vb[c*VSTR + q*8] = *(const uint4*)(vhg + (size_t)c*NPIX + j0 + q*8);
        }
        __syncthreads();

        // ---- QK fp16-split: S slab 16x32 per warp, 2x k16 steps ----
        float sfr[4][4];
        #pragma unroll
        for (int nt=0;nt<4;nt++)
            #pragma unroll
            for (int q=0;q<4;q++) sfr[nt][q] = 0.f;
        #pragma unroll
        for (int ks=0; ks<2; ks++){
            int kb = ks*8;
            uint32_t ah[4], alr[4];
            ah[0]  = Qh32[(m0+g  )*QKS + kb+tig];
            ah[1]  = Qh32[(m0+g+8)*QKS + kb+tig];
            ah[2]  = Qh32[(m0+g  )*QKS + kb+tig+4];
            ah[3]  = Qh32[(m0+g+8)*QKS + kb+tig+4];
            alr[0] = Ql32[(m0+g  )*QKS + kb+tig];
            alr[1] = Ql32[(m0+g+8)*QKS + kb+tig];
            alr[2] = Ql32[(m0+g  )*QKS + kb+tig+4];
            alr[3] = Ql32[(m0+g+8)*QKS + kb+tig+4];
            #pragma unroll
            for (int nt=0;nt<4;nt++){
                int jr = nqk0 + nt*8 + g;
                uint32_t bh0 = Kh32[jr*QKS + kb+tig], bh1 = Kh32[jr*QKS + kb+tig+4];
                uint32_t bl0 = Kl32[jr*QKS + kb+tig], bl1 = Kl32[jr*QKS + kb+tig+4];
                mma_f16(sfr[nt], ah,  bh0, bh1);
                mma_f16(sfr[nt], alr, bh0, bh1);
                mma_f16(sfr[nt], ah,  bl0, bl1);
            }
        }

        // softmax phase 1: partial row max
        float pm0 = sfr[0][0], pm1 = sfr[0][2];
        #pragma unroll
        for (int nt=0;nt<4;nt++){
            pm0 = fmaxf(pm0, fmaxf(sfr[nt][0], sfr[nt][1]));
            pm1 = fmaxf(pm1, fmaxf(sfr[nt][2], sfr[nt][3]));
        }
        pm0 = fmaxf(pm0, __shfl_xor_sync(0xffffffffu, pm0, 1));
        pm0 = fmaxf(pm0, __shfl_xor_sync(0xffffffffu, pm0, 2));
        pm1 = fmaxf(pm1, __shfl_xor_sync(0xffffffffu, pm1, 1));
        pm1 = fmaxf(pm1, __shfl_xor_sync(0xffffffffu, pm1, 2));
        if (tig == 0){
            pmax2[wc*64 + m0+g  ] = pm0;
            pmax2[wc*64 + m0+g+8] = pm1;
        }
        __syncthreads();

        // phase 2: P = exp(S - m_new), partial sums, store fp16 P
        {
            const int r0 = m0+g, r1 = m0+g+8;
            float mn0 = fmaxf(row_m[r0], fmaxf(pmax2[r0], pmax2[64+r0]));
            float mn1 = fmaxf(row_m[r1], fmaxf(pmax2[r1], pmax2[64+r1]));
            float ts0 = 0.f, ts1 = 0.f;
            #pragma unroll
            for (int nt=0;nt<4;nt++){
                int cb2 = nqk0 + nt*8 + 2*tig;
                float p00 = __expf(sfr[nt][0]-mn0), p01 = __expf(sfr[nt][1]-mn0);
                float p10 = __expf(sfr[nt][2]-mn1), p11 = __expf(sfr[nt][3]-mn1);
                ts0 += p00+p01;  ts1 += p10+p11;
                *(uint32_t*)&Pb[r0*VSTR + cb2] = f16pack(p00, p01);
                *(uint32_t*)&Pb[r1*VSTR + cb2] = f16pack(p10, p11);
            }
            ts0 += __shfl_xor_sync(0xffffffffu, ts0, 1);
            ts0 += __shfl_xor_sync(0xffffffffu, ts0, 2);
            ts1 += __shfl_xor_sync(0xffffffffu, ts1, 1);
            ts1 += __shfl_xor_sync(0xffffffffu, ts1, 2);
            if (tig == 0){ psum2[wc*64+r0] = ts0; psum2[wc*64+r1] = ts1; }
        }
        __syncthreads();

        // phase 3: row state (single writer per row)
        if (wc == 0 && tig == 0){
            #pragma unroll
            for (int h=0;h<2;h++){
                int r = m0 + g + h*8;
                float mo = row_m[r];
                float mn = fmaxf(mo, fmaxf(pmax2[r], pmax2[64+r]));
                float sc = __expf(mo - mn);
                row_sc[r] = sc;
                row_l[r]  = row_l[r]*sc + psum2[r] + psum2[64+r];
                row_m[r]  = mn;
            }
        }
        __syncthreads();

        // ---- PV: rescale accumulators, then fp16 m16n8k16 MMA ----
        float s0v[8], s1v[8];
        bool need = false;
        #pragma unroll
        for (int nt=0;nt<8;nt++){
            s0v[nt] = row_sc[nt*8 + 2*tig];
            s1v[nt] = row_sc[nt*8 + 2*tig + 1];
            need |= (s0v[nt] != 1.f) | (s1v[nt] != 1.f);
        }
        if (__ballot_sync(0xffffffffu, need)){
            #pragma unroll
            for (int mt=0;mt<2;mt++)
                #pragma unroll
                for (int nt=0;nt<8;nt++){
                    d_acc[mt][nt][0] *= s0v[nt];  d_acc[mt][nt][1] *= s1v[nt];
                    d_acc[mt][nt][2] *= s0v[nt];  d_acc[mt][nt][3] *= s1v[nt];
                }
        }
        #pragma unroll
        for (int ks=0; ks<4; ks++){
            int k0 = ks*16;
            uint32_t A0[4], A1[4];
            A0[0] = *(const uint32_t*)&Vb[(c0+g   )*VSTR + k0+2*tig  ];
            A0[1] = *(const uint32_t*)&Vb[(c0+g+8 )*VSTR + k0+2*tig  ];
            A0[2] = *(const uint32_t*)&Vb[(c0+g   )*VSTR + k0+2*tig+8];
            A0[3] = *(const uint32_t*)&Vb[(c0+g+8 )*VSTR + k0+2*tig+8];
            A1[0] = *(const uint32_t*)&Vb[(c0+g+16)*VSTR + k0+2*tig  ];
            A1[1] = *(const uint32_t*)&Vb[(c0+g+24)*VSTR + k0+2*tig  ];
            A1[2] = *(const uint32_t*)&Vb[(c0+g+16)*VSTR + k0+2*tig+8];
            A1[3] = *(const uint32_t*)&Vb[(c0+g+24)*VSTR + k0+2*tig+8];
            #pragma unroll
            for (int nt=0;nt<8;nt++){
                uint32_t b0 = *(const uint32_t*)&Pb[(nt*8+g)*VSTR + k0+2*tig  ];
                uint32_t b1 = *(const uint32_t*)&Pb[(nt*8+g)*VSTR + k0+2*tig+8];
                mma_f16(d_acc[0][nt], A0, b0, b1);
                mma_f16(d_acc[1][nt], A1, b0, b1);
            }
        }
    }

    // ---- epilogue ----
    __syncthreads();
    if (t < 64) row_rl[t] = 1.f / row_l[t];
    __syncthreads();

    const float gam = gamma[0];
    float rl0[8], rl1[8];
    #pragma unroll
    for (int nt=0;nt<8;nt++){
        rl0[nt] = row_rl[nt*8 + 2*tig];
        rl1[nt] = row_rl[nt*8 + 2*tig + 1];
    }
    const int cta = b*NQT + blockIdx.x;
    #pragma unroll
    for (int mt=0;mt<2;mt++){
        #pragma unroll
        for (int h=0;h<2;h++){
            int c = c0 + mt*16 + g + h*8;
            size_t base = ((size_t)b*CCH + c)*NPIX + i0;
            float accs = 0.f, accq = 0.f;
            #pragma unroll
            for (int nt=0;nt<8;nt++){
                int i = nt*8 + 2*tig;
                float2 xv = *(const float2*)(x + base + i);
                float y0 = gam*d_acc[mt][nt][h*2+0]*rl0[nt] + xv.x;
                float y1 = gam*d_acc[mt][nt][h*2+1]*rl1[nt] + xv.y;
                *(float2*)(g_y + base + i) = make_float2(y0, y1);
                accs += y0 + y1;
                accq += y0*y0 + y1*y1;
            }
            accs += __shfl_xor_sync(0xffffffffu, accs, 1);
            accs += __shfl_xor_sync(0xffffffffu, accs, 2);
            accq += __shfl_xor_sync(0xffffffffu, accq, 1);
            accq += __shfl_xor_sync(0xffffffffu, accq, 2);
            if (tig == 0){
                g_psum[cta*CCH + c] = accs;
                g_psq [cta*CCH + c] = accq;
            }
        }
    }
}

// ---------------- Kernel C1: BN stat reduce -------------------------------
__global__ __launch_bounds__(256) void bnstat_kernel(
    const float* __restrict__ bnw, const float* __restrict__ bnb)
{
    __shared__ float ss[256], sq[256];
    const int c = blockIdx.x, t = threadIdx.x;
    float s = g_psum[t*CCH + c] + g_psum[(t+256)*CCH + c];
    float q = g_psq [t*CCH + c] + g_psq [(t+256)*CCH + c];
    ss[t]=s; sq[t]=q;
    __syncthreads();
    for (int off=128; off>0; off>>=1){
        if (t<off){ ss[t]+=ss[t+off]; sq[t]+=sq[t+off]; }
        __syncthreads();
    }
    if (t==0){
        const float inv = 1.f/32768.f;
        float mean = ss[0]*inv;
        float var  = sq[0]*inv - mean*mean;
        float scale = bnw[c]*rsqrtf(var + 1e-5f);
        g_bn[c]       = scale;
        g_bn[CCH + c] = bnb[c] - mean*scale;
    }
}

// ---------------- Kernel C2: BN apply + ReLU ------------------------------
__global__ __launch_bounds__(256) void bnapply_kernel(float* __restrict__ out)
{
    int idx = blockIdx.x*256 + threadIdx.x;
    int c = (idx >> 10) & 255;
    float scale = g_bn[c], shift = g_bn[CCH + c];
    float4 y = ((const float4*)g_y)[idx];
    float4 o;
    o.x = fmaxf(y.x*scale + shift, 0.f);
    o.y = fmaxf(y.y*scale + shift, 0.f);
    o.z = fmaxf(y.z*scale + shift, 0.f);
    o.w = fmaxf(y.w*scale + shift, 0.f);
    ((float4*)out)[idx] = o;
}

// ---------------------------------------------------------------------------
extern "C" void kernel_launch(void* const* d_in, const int* in_sizes, int n_in,
                              void* d_out, int out_size)
{
    const float* x     = (const float*)d_in[0];
    const float* wq    = (const float*)d_in[1];
    const float* bq    = (const float*)d_in[2];
    const float* wk    = (const float*)d_in[3];
    const float* bk    = (const float*)d_in[4];
    const float* wv    = (const float*)d_in[5];
    const float* bv    = (const float*)d_in[6];
    const float* gamma = (const float*)d_in[7];
    const float* bnw   = (const float*)d_in[8];
    const float* bnb   = (const float*)d_in[9];
    float* out = (float*)d_out;

    dim3 gA(NPIX/128, 5, BATCH);
    projmma_kernel<<<gA, 256>>>(x, wq, bq, wk, bk, wv, bv);

    qkpack_kernel<<<(BATCH*32*NPIX/4)/256, 256>>>();

    const int attn_smem = (256*VSTR + 64*VSTR)*2 + (4*64*QKS)*4 + (128+128+64*4)*4; // 67,584 B
    cudaFuncSetAttribute(attn_kernel, cudaFuncAttributeMaxDynamicSharedMemorySize, attn_smem);
    attn_kernel<<<dim3(NQT, BATCH), 256, attn_smem>>>(x, gamma);

    bnstat_kernel<<<CCH, 256>>>(bnw, bnb);

    bnapply_kernel<<<(BATCH*CCH*NPIX)/(256*4), 256>>>(out);
}

// round 17
// speedup vs baseline: 1.0308x; 1.0308x over previous
#include <cuda_runtime.h>
#include <cuda_fp16.h>
#include <cstdint>

#define BATCH 8
#define CCH   256
#define NPIX  4096
#define TQ    64
#define TK    64
#define NQT   (NPIX/TQ)
#define NCTA_ATTN (BATCH*NQT)

__device__ __align__(16) float g_proj[(size_t)BATCH*64*NPIX];   // rows 0-31 q, 32-63 k (fp32)
__device__ __align__(16) __half g_vh[(size_t)BATCH*CCH*NPIX];   // V in fp16
__device__ __align__(16) uint32_t g_qkh[(size_t)BATCH*32*NPIX]; // fp16x2 hi: planes 0-15 Q, 16-31 K
__device__ __align__(16) uint32_t g_qkl[(size_t)BATCH*32*NPIX]; // fp16x2 lo
__device__ __align__(16) float g_y[(size_t)BATCH*CCH*NPIX];
__device__ __align__(16) float g_psum[NCTA_ATTN*CCH];
__device__ __align__(16) float g_psq[NCTA_ATTN*CCH];
__device__ __align__(16) float g_bn[2*CCH];

__device__ __forceinline__ uint32_t f2tf(float f){
    uint32_t r; asm("cvt.rna.tf32.f32 %0, %1;" : "=r"(r) : "f"(f)); return r;
}
__device__ __forceinline__ uint32_t f16pack(float lo, float hi){
    uint32_t r; asm("cvt.rn.f16x2.f32 %0, %1, %2;" : "=r"(r) : "f"(hi), "f"(lo)); return r;
}
__device__ __forceinline__ void mma_tf32(float* d, const uint32_t* a, uint32_t b0, uint32_t b1){
    asm("mma.sync.aligned.m16n8k8.row.col.f32.tf32.tf32.f32 "
        "{%0,%1,%2,%3},{%4,%5,%6,%7},{%8,%9},{%0,%1,%2,%3};"
        : "+f"(d[0]), "+f"(d[1]), "+f"(d[2]), "+f"(d[3])
        : "r"(a[0]), "r"(a[1]), "r"(a[2]), "r"(a[3]), "r"(b0), "r"(b1));
}
__device__ __forceinline__ void mma_f16(float* d, const uint32_t* a, uint32_t b0, uint32_t b1){
    asm("mma.sync.aligned.m16n8k16.row.col.f32.f16.f16.f32 "
        "{%0,%1,%2,%3},{%4,%5,%6,%7},{%8,%9},{%0,%1,%2,%3};"
        : "+f"(d[0]), "+f"(d[1]), "+f"(d[2]), "+f"(d[3])
        : "r"(a[0]), "r"(a[1]), "r"(a[2]), "r"(a[3]), "r"(b0), "r"(b1));
}
__device__ __forceinline__ uint32_t smem_u32(const void* p){
    uint32_t a;
    asm("{ .reg .u64 t; cvta.to.shared.u64 t, %1; cvt.u32.u64 %0, t; }" : "=r"(a) : "l"(p));
    return a;
}
#define CP_ASYNC4(dst, src)  asm volatile("cp.async.ca.shared.global [%0], [%1], 4;"  :: "r"(dst), "l"(src))
#define CP_ASYNC16(dst, src) asm volatile("cp.async.cg.shared.global [%0], [%1], 16;" :: "r"(dst), "l"(src))
#define CP_COMMIT()          asm volatile("cp.async.commit_group;" ::: "memory")
#define CP_WAIT1()           asm volatile("cp.async.wait_group 1;" ::: "memory")

// ---------------- Kernel A: projection GEMM on tensor cores ----------------
__global__ __launch_bounds__(256) void projmma_kernel(
    const float* __restrict__ x,
    const float* __restrict__ wq, const float* __restrict__ bq,
    const float* __restrict__ wk, const float* __restrict__ bk,
    const float* __restrict__ wv, const float* __restrict__ bv)
{
    __shared__ float Ws[64*36];
    __shared__ float Xs[32*136];
    const int t  = threadIdx.x;
    const int w  = t >> 5, l = t & 31;
    const int g  = l >> 2, tig = l & 3;
    const int wm = w & 1, wn = w >> 1;
    const int m0 = wm*32, nw0 = wn*32;
    const int n0 = blockIdx.x*128;
    const int rowbase = blockIdx.y*64;
    const int b  = blockIdx.z;
    const bool is_qk = (blockIdx.y == 0);
    const float* xb = x + (size_t)b*CCH*NPIX;

    float acc[2][4][4];
    #pragma unroll
    for (int mt=0;mt<2;mt++)
        #pragma unroll
        for (int nt=0;nt<4;nt++)
            #pragma unroll
            for (int q=0;q<4;q++) acc[mt][nt][q] = 0.f;

    for (int k0=0; k0<CCH; k0+=32){
        __syncthreads();
        #pragma unroll
        for (int it=0; it<8; it++){
            int e = it*256 + t;
            int r = e >> 5, kk = e & 31;
            int grow = rowbase + r;
            const float* ws; int lr;
            if (grow < 32)      { ws = wq; lr = grow; }
            else if (grow < 64) { ws = wk; lr = grow-32; }
            else                { ws = wv; lr = grow-64; }
            Ws[r*36 + kk] = ws[(size_t)lr*CCH + k0 + kk];
        }
        #pragma unroll
        for (int it=0; it<4; it++){
            int e = it*256 + t;
            int kk = e >> 5, c4 = (e & 31)*4;
            *(float4*)&Xs[kk*136 + c4] = *(const float4*)(xb + (size_t)(k0+kk)*NPIX + n0 + c4);
        }
        __syncthreads();
        #pragma unroll
        for (int ks=0; ks<4; ks++){
            int k8 = ks*8;
            uint32_t ah[2][4], al[2][4];
            #pragma unroll
            for (int mt=0;mt<2;mt++){
                int rb = m0 + mt*16;
                float a0 = Ws[(rb+g  )*36 + k8+tig];
                float a1 = Ws[(rb+g+8)*36 + k8+tig];
                float a2 = Ws[(rb+g  )*36 + k8+tig+4];
                float a3 = Ws[(rb+g+8)*36 + k8+tig+4];
                ah[mt][0]=f2tf(a0); ah[mt][1]=f2tf(a1); ah[mt][2]=f2tf(a2); ah[mt][3]=f2tf(a3);
                if (is_qk){
                    al[mt][0]=f2tf(a0-__uint_as_float(ah[mt][0]));
                    al[mt][1]=f2tf(a1-__uint_as_float(ah[mt][1]));
                    al[mt][2]=f2tf(a2-__uint_as_float(ah[mt][2]));
                    al[mt][3]=f2tf(a3-__uint_as_float(ah[mt][3]));
                }
            }
            uint32_t bh[4][2], bl[4][2];
            #pragma unroll
            for (int nt=0;nt<4;nt++){
                int jn = nw0 + nt*8 + g;
                float b0 = Xs[(k8+tig  )*136 + jn];
                float b1 = Xs[(k8+tig+4)*136 + jn];
                bh[nt][0]=f2tf(b0); bh[nt][1]=f2tf(b1);
                if (is_qk){
                    bl[nt][0]=f2tf(b0-__uint_as_float(bh[nt][0]));
                    bl[nt][1]=f2tf(b1-__uint_as_float(bh[nt][1]));
                }
            }
            #pragma unroll
            for (int mt=0;mt<2;mt++)
                #pragma unroll
                for (int nt=0;nt<4;nt++){
                    mma_tf32(acc[mt][nt], ah[mt], bh[nt][0], bh[nt][1]);
                    if (is_qk){
                        mma_tf32(acc[mt][nt], al[mt], bh[nt][0], bh[nt][1]);
                        mma_tf32(acc[mt][nt], ah[mt], bl[nt][0], bl[nt][1]);
                    }
                }
        }
    }
    #pragma unroll
    for (int mt=0;mt<2;mt++){
        #pragma unroll
        for (int h=0;h<2;h++){
            int lrow = m0 + mt*16 + g + h*8;
            int grow = rowbase + lrow;
            float bias;
            if (grow < 32)      bias = bq[grow];
            else if (grow < 64) bias = bk[grow-32];
            else                bias = bv[grow-64];
            #pragma unroll
            for (int nt=0;nt<4;nt++){
                int pix = n0 + nw0 + nt*8 + 2*tig;
                float v0 = acc[mt][nt][h*2+0] + bias;
                float v1 = acc[mt][nt][h*2+1] + bias;
                if (is_qk){
                    *(float2*)(g_proj + ((size_t)b*64 + grow)*NPIX + pix) = make_float2(v0, v1);
                } else {
                    *(uint32_t*)&g_vh[((size_t)b*CCH + (grow-64))*NPIX + pix] = f16pack(v0, v1);
                }
            }
        }
    }
}

// ---------------- Kernel A2: pack Q/K into fp16 hi/lo planes ---------------
__global__ __launch_bounds__(256) void qkpack_kernel()
{
    int e = blockIdx.x*256 + threadIdx.x;
    int pix = (e & 1023) * 4;
    int plane = (e >> 10) & 31;
    int b = e >> 15;
    const float* r0 = g_proj + ((size_t)b*64 + 2*plane)*NPIX + pix;
    const float* r1 = r0 + NPIX;
    float4 v0 = *(const float4*)r0;
    float4 v1 = *(const float4*)r1;
    uint4 hp, lp;
    float a0, a1;
    a0 = v0.x; a1 = v1.x;
    { __half h0=__float2half_rn(a0), h1=__float2half_rn(a1);
      hp.x = ((uint32_t)(*(uint16_t*)&h1)<<16)|(*(uint16_t*)&h0);
      lp.x = f16pack(a0-__half2float(h0), a1-__half2float(h1)); }
    a0 = v0.y; a1 = v1.y;
    { __half h0=__float2half_rn(a0), h1=__float2half_rn(a1);
      hp.y = ((uint32_t)(*(uint16_t*)&h1)<<16)|(*(uint16_t*)&h0);
      lp.y = f16pack(a0-__half2float(h0), a1-__half2float(h1)); }
    a0 = v0.z; a1 = v1.z;
    { __half h0=__float2half_rn(a0), h1=__float2half_rn(a1);
      hp.z = ((uint32_t)(*(uint16_t*)&h1)<<16)|(*(uint16_t*)&h0);
      lp.z = f16pack(a0-__half2float(h0), a1-__half2float(h1)); }
    a0 = v0.w; a1 = v1.w;
    { __half h0=__float2half_rn(a0), h1=__float2half_rn(a1);
      hp.w = ((uint32_t)(*(uint16_t*)&h1)<<16)|(*(uint16_t*)&h0);
      lp.w = f16pack(a0-__half2float(h0), a1-__half2float(h1)); }
    *(uint4*)&g_qkh[((size_t)b*32 + plane)*NPIX + pix] = hp;
    *(uint4*)&g_qkl[((size_t)b*32 + plane)*NPIX + pix] = lp;
}

// ---------------- Kernel B: flash attention, cp.async pipelined ------------
// QK: fp16-split (3 chains).  PV: fp16 m16n8k16.
// K double-buffered via cp.async (hidden under softmax+PV of prev tile);
// V issued at tile top, waited just before PV (hidden under QK+softmax).
#define VSTR 72
#define QKS  20
// byte offsets in dynamic smem
#define OF_VB   0
#define OF_PB   36864
#define OF_QH   46080
#define OF_QL   51200
#define OF_KB   56320          /* 2 bufs x (Kh 5120 + Kl 5120) */
#define OF_RED  76800
#define ATTN_SMEM 78848

__global__ __launch_bounds__(256,2) void attn_kernel(
    const float* __restrict__ x, const float* __restrict__ gamma)
{
    extern __shared__ char sm[];
    const uint32_t smb = smem_u32(sm);
    __half* Vb = (__half*)(sm + OF_VB);
    __half* Pb = (__half*)(sm + OF_PB);
    uint32_t* Qh32 = (uint32_t*)(sm + OF_QH);
    uint32_t* Ql32 = (uint32_t*)(sm + OF_QL);
    float* pmax2 = (float*)(sm + OF_RED);
    float* psum2 = pmax2 + 128;
    float* row_m = psum2 + 128;
    float* row_l = row_m + 64;
    float* row_sc= row_l + 64;
    float* row_rl= row_sc + 64;

    const int t  = threadIdx.x;
    const int w  = t >> 5, l = t & 31;
    const int g  = l >> 2, tig = l & 3;
    const int b  = blockIdx.y;
    const int i0 = blockIdx.x * TQ;
    const uint32_t* qh = g_qkh + (size_t)b*32*NPIX;
    const uint32_t* ql = g_qkl + (size_t)b*32*NPIX;
    const uint32_t* kh = qh + (size_t)16*NPIX;
    const uint32_t* kl = ql + (size_t)16*NPIX;
    const __half* vhg = g_vh + (size_t)b*CCH*NPIX;

    // stage Q once (plain loads)
    #pragma unroll
    for (int it=0; it<4; it++){
        int p = it*256 + t;
        int i = p & 63, dp = p >> 6;
        Qh32[i*QKS + dp] = qh[(size_t)dp*NPIX + i0 + i];
        Ql32[i*QKS + dp] = ql[(size_t)dp*NPIX + i0 + i];
    }
    if (t < 64){ row_m[t] = -1e30f; row_l[t] = 0.f; }

    // per-thread K staging coords (8 x 4B per buffer)
    const int kj  = t & 63;        // j within tile
    const int kdp = t >> 6;        // 0..3 -> dp = kdp, kdp+4... use 2 groups of 4
    // thread handles dp = kdp and kdp+4, for hi and lo planes (4 cp.async x 2 sets)

    // prologue: K_0 into buffer 0
    {
        uint32_t kb0 = smb + OF_KB;
        #pragma unroll
        for (int s=0; s<2; s++){
            int dp = kdp + s*4;
            CP_ASYNC4(kb0        + (kj*QKS + dp)*4, kh + (size_t)dp*NPIX + kj);
            CP_ASYNC4(kb0 + 5120 + (kj*QKS + dp)*4, kl + (size_t)dp*NPIX + kj);
            int dp2 = dp + 8;
            CP_ASYNC4(kb0        + (kj*QKS + dp2)*4, kh + (size_t)dp2*NPIX + kj);
            CP_ASYNC4(kb0 + 5120 + (kj*QKS + dp2)*4, kl + (size_t)dp2*NPIX + kj);
        }
        CP_COMMIT();
    }

    const int wb = w & 3, wc = w >> 2;
    const int m0 = wb*16, nqk0 = wc*32;
    const int c0 = w*32;

    float d_acc[2][8][4];
    #pragma unroll
    for (int mt=0;mt<2;mt++)
        #pragma unroll
        for (int nt=0;nt<8;nt++)
            #pragma unroll
            for (int q=0;q<4;q++) d_acc[mt][nt][q] = 0.f;

    int tile = 0;
    for (int j0=0; j0<NPIX; j0+=TK, ++tile){
        __syncthreads();   // Vb/Pb free (prev PV done); Q stores visible (tile 0)

        // issue V_tile cp.async into Vb (single buffer, safe after barrier)
        #pragma unroll
        for (int it=0; it<8; it++){
            int e = it*256 + t;
            int c = e >> 3, q = e & 7;
            CP_ASYNC16(smb + OF_VB + (c*VSTR + q*8)*2, vhg + (size_t)c*NPIX + j0 + q*8);
        }
        CP_COMMIT();       // pending: [K_tile][V_tile]
        CP_WAIT1();        // K_tile complete
        __syncthreads();   // K visible to all threads

        const uint32_t* Kh32 = (const uint32_t*)(sm + OF_KB + (tile&1)*10240);
        const uint32_t* Kl32 = Kh32 + 64*QKS;

        // ---- QK fp16-split ----
        float sfr[4][4];
        #pragma unroll
        for (int nt=0;nt<4;nt++)
            #pragma unroll
            for (int q=0;q<4;q++) sfr[nt][q] = 0.f;
        #pragma unroll
        for (int ks=0; ks<2; ks++){
            int kb = ks*8;
            uint32_t ah[4], alr[4];
            ah[0]  = Qh32[(m0+g  )*QKS + kb+tig];
            ah[1]  = Qh32[(m0+g+8)*QKS + kb+tig];
            ah[2]  = Qh32[(m0+g  )*QKS + kb+tig+4];
            ah[3]  = Qh32[(m0+g+8)*QKS + kb+tig+4];
            alr[0] = Ql32[(m0+g  )*QKS + kb+tig];
            alr[1] = Ql32[(m0+g+8)*QKS + kb+tig];
            alr[2] = Ql32[(m0+g  )*QKS + kb+tig+4];
            alr[3] = Ql32[(m0+g+8)*QKS + kb+tig+4];
            #pragma unroll
            for (int nt=0;nt<4;nt++){
                int jr = nqk0 + nt*8 + g;
                uint32_t bh0 = Kh32[jr*QKS + kb+tig], bh1 = Kh32[jr*QKS + kb+tig+4];
                uint32_t bl0 = Kl32[jr*QKS + kb+tig], bl1 = Kl32[jr*QKS + kb+tig+4];
                mma_f16(sfr[nt], ah,  bh0, bh1);
                mma_f16(sfr[nt], alr, bh0, bh1);
                mma_f16(sfr[nt], ah,  bl0, bl1);
            }
        }

        // prefetch K_{tile+1} into alternate buffer (overlaps softmax+PV)
        if (j0 + TK < NPIX){
            uint32_t kbn = smb + OF_KB + ((tile+1)&1)*10240;
            int jn0 = j0 + TK;
            #pragma unroll
            for (int s=0; s<2; s++){
                int dp = kdp + s*4;
                CP_ASYNC4(kbn        + (kj*QKS + dp)*4, kh + (size_t)dp*NPIX + jn0 + kj);
                CP_ASYNC4(kbn + 5120 + (kj*QKS + dp)*4, kl + (size_t)dp*NPIX + jn0 + kj);
                int dp2 = dp + 8;
                CP_ASYNC4(kbn        + (kj*QKS + dp2)*4, kh + (size_t)dp2*NPIX + jn0 + kj);
                CP_ASYNC4(kbn + 5120 + (kj*QKS + dp2)*4, kl + (size_t)dp2*NPIX + jn0 + kj);
            }
        }
        CP_COMMIT();       // pending: [V_tile][K_next] (K_next may be empty group)

        // softmax phase 1: partial row max
        float pm0 = sfr[0][0], pm1 = sfr[0][2];
        #pragma unroll
        for (int nt=0;nt<4;nt++){
            pm0 = fmaxf(pm0, fmaxf(sfr[nt][0], sfr[nt][1]));
            pm1 = fmaxf(pm1, fmaxf(sfr[nt][2], sfr[nt][3]));
        }
        pm0 = fmaxf(pm0, __shfl_xor_sync(0xffffffffu, pm0, 1));
        pm0 = fmaxf(pm0, __shfl_xor_sync(0xffffffffu, pm0, 2));
        pm1 = fmaxf(pm1, __shfl_xor_sync(0xffffffffu, pm1, 1));
        pm1 = fmaxf(pm1, __shfl_xor_sync(0xffffffffu, pm1, 2));
        if (tig == 0){
            pmax2[wc*64 + m0+g  ] = pm0;
            pmax2[wc*64 + m0+g+8] = pm1;
        }
        __syncthreads();

        // phase 2: P = exp(S - m_new), partial sums, store fp16 P
        {
            const int r0 = m0+g, r1 = m0+g+8;
            float mn0 = fmaxf(row_m[r0], fmaxf(pmax2[r0], pmax2[64+r0]));
            float mn1 = fmaxf(row_m[r1], fmaxf(pmax2[r1], pmax2[64+r1]));
            float ts0 = 0.f, ts1 = 0.f;
            #pragma unroll
            for (int nt=0;nt<4;nt++){
                int cb2 = nqk0 + nt*8 + 2*tig;
                float p00 = __expf(sfr[nt][0]-mn0), p01 = __expf(sfr[nt][1]-mn0);
                float p10 = __expf(sfr[nt][2]-mn1), p11 = __expf(sfr[nt][3]-mn1);
                ts0 += p00+p01;  ts1 += p10+p11;
                *(uint32_t*)&Pb[r0*VSTR + cb2] = f16pack(p00, p01);
                *(uint32_t*)&Pb[r1*VSTR + cb2] = f16pack(p10, p11);
            }
            ts0 += __shfl_xor_sync(0xffffffffu, ts0, 1);
            ts0 += __shfl_xor_sync(0xffffffffu, ts0, 2);
            ts1 += __shfl_xor_sync(0xffffffffu, ts1, 1);
            ts1 += __shfl_xor_sync(0xffffffffu, ts1, 2);
            if (tig == 0){ psum2[wc*64+r0] = ts0; psum2[wc*64+r1] = ts1; }
        }
        __syncthreads();

        // phase 3: row state (single writer per row)
        if (wc == 0 && tig == 0){
            #pragma unroll
            for (int h=0;h<2;h++){
                int r = m0 + g + h*8;
                float mo = row_m[r];
                float mn = fmaxf(mo, fmaxf(pmax2[r], pmax2[64+r]));
                float sc = __expf(mo - mn);
                row_sc[r] = sc;
                row_l[r]  = row_l[r]*sc + psum2[r] + psum2[64+r];
                row_m[r]  = mn;
            }
        }
        CP_WAIT1();        // V_tile complete (K_next may still be in flight)
        __syncthreads();   // V + row state visible

        // ---- PV: rescale accumulators, then fp16 m16n8k16 MMA ----
        float s0v[8], s1v[8];
        bool need = false;
        #pragma unroll
        for (int nt=0;nt<8;nt++){
            s0v[nt] = row_sc[nt*8 + 2*tig];
            s1v[nt] = row_sc[nt*8 + 2*tig + 1];
            need |= (s0v[nt] != 1.f) | (s1v[nt] != 1.f);
        }
        if (__ballot_sync(0xffffffffu, need)){
            #pragma unroll
            for (int mt=0;mt<2;mt++)
                #pragma unroll
                for (int nt=0;nt<8;nt++){
                    d_acc[mt][nt][0] *= s0v[nt];  d_acc[mt][nt][1] *= s1v[nt];
                    d_acc[mt][nt][2] *= s0v[nt];  d_acc[mt][nt][3] *= s1v[nt];
                }
        }
        #pragma unroll
        for (int ks=0; ks<4; ks++){
            int k0 = ks*16;
            uint32_t A0[4], A1[4];
            A0[0] = *(const uint32_t*)&Vb[(c0+g   )*VSTR + k0+2*tig  ];
            A0[1] = *(const uint32_t*)&Vb[(c0+g+8 )*VSTR + k0+2*tig  ];
            A0[2] = *(const uint32_t*)&Vb[(c0+g   )*VSTR + k0+2*tig+8];
            A0[3] = *(const uint32_t*)&Vb[(c0+g+8 )*VSTR + k0+2*tig+8];
            A1[0] = *(const uint32_t*)&Vb[(c0+g+16)*VSTR + k0+2*tig  ];
            A1[1] = *(const uint32_t*)&Vb[(c0+g+24)*VSTR + k0+2*tig  ];
            A1[2] = *(const uint32_t*)&Vb[(c0+g+16)*VSTR + k0+2*tig+8];
            A1[3] = *(const uint32_t*)&Vb[(c0+g+24)*VSTR + k0+2*tig+8];
            #pragma unroll
            for (int nt=0;nt<8;nt++){
                uint32_t b0 = *(const uint32_t*)&Pb[(nt*8+g)*VSTR + k0+2*tig  ];
                uint32_t b1 = *(const uint32_t*)&Pb[(nt*8+g)*VSTR + k0+2*tig+8];
                mma_f16(d_acc[0][nt], A0, b0, b1);
                mma_f16(d_acc[1][nt], A1, b0, b1);
            }
        }
    }

    // ---- epilogue ----
    __syncthreads();
    if (t < 64) row_rl[t] = 1.f / row_l[t];
    __syncthreads();

    const float gam = gamma[0];
    float rl0[8], rl1[8];
    #pragma unroll
    for (int nt=0;nt<8;nt++){
        rl0[nt] = row_rl[nt*8 + 2*tig];
        rl1[nt] = row_rl[nt*8 + 2*tig + 1];
    }
    const int cta = b*NQT + blockIdx.x;
    #pragma unroll
    for (int mt=0;mt<2;mt++){
        #pragma unroll
        for (int h=0;h<2;h++){
            int c = c0 + mt*16 + g + h*8;
            size_t base = ((size_t)b*CCH + c)*NPIX + i0;
            float accs = 0.f, accq = 0.f;
            #pragma unroll
            for (int nt=0;nt<8;nt++){
                int i = nt*8 + 2*tig;
                float2 xv = *(const float2*)(x + base + i);
                float y0 = gam*d_acc[mt][nt][h*2+0]*rl0[nt] + xv.x;
                float y1 = gam*d_acc[mt][nt][h*2+1]*rl1[nt] + xv.y;
                *(float2*)(g_y + base + i) = make_float2(y0, y1);
                accs += y0 + y1;
                accq += y0*y0 + y1*y1;
            }
            accs += __shfl_xor_sync(0xffffffffu, accs, 1);
            accs += __shfl_xor_sync(0xffffffffu, accs, 2);
            accq += __shfl_xor_sync(0xffffffffu, accq, 1);
            accq += __shfl_xor_sync(0xffffffffu, accq, 2);
            if (tig == 0){
                g_psum[cta*CCH + c] = accs;
                g_psq [cta*CCH + c] = accq;
            }
        }
    }
}

// ---------------- Kernel C1: BN stat reduce -------------------------------
__global__ __launch_bounds__(256) void bnstat_kernel(
    const float* __restrict__ bnw, const float* __restrict__ bnb)
{
    __shared__ float ss[256], sq[256];
    const int c = blockIdx.x, t = threadIdx.x;
    float s = g_psum[t*CCH + c] + g_psum[(t+256)*CCH + c];
    float q = g_psq [t*CCH + c] + g_psq [(t+256)*CCH + c];
    ss[t]=s; sq[t]=q;
    __syncthreads();
    for (int off=128; off>0; off>>=1){
        if (t<off){ ss[t]+=ss[t+off]; sq[t]+=sq[t+off]; }
        __syncthreads();
    }
    if (t==0){
        const float inv = 1.f/32768.f;
        float mean = ss[0]*inv;
        float var  = sq[0]*inv - mean*mean;
        float scale = bnw[c]*rsqrtf(var + 1e-5f);
        g_bn[c]       = scale;
        g_bn[CCH + c] = bnb[c] - mean*scale;
    }
}

// ---------------- Kernel C2: BN apply + ReLU ------------------------------
__global__ __launch_bounds__(256) void bnapply_kernel(float* __restrict__ out)
{
    int idx = blockIdx.x*256 + threadIdx.x;
    int c = (idx >> 10) & 255;
    float scale = g_bn[c], shift = g_bn[CCH + c];
    float4 y = ((const float4*)g_y)[idx];
    float4 o;
    o.x = fmaxf(y.x*scale + shift, 0.f);
    o.y = fmaxf(y.y*scale + shift, 0.f);
    o.z = fmaxf(y.z*scale + shift, 0.f);
    o.w = fmaxf(y.w*scale + shift, 0.f);
    ((float4*)out)[idx] = o;
}

// ---------------------------------------------------------------------------
extern "C" void kernel_launch(void* const* d_in, const int* in_sizes, int n_in,
                              void* d_out, int out_size)
{
    const float* x     = (const float*)d_in[0];
    const float* wq    = (const float*)d_in[1];
    const float* bq    = (const float*)d_in[2];
    const float* wk    = (const float*)d_in[3];
    const float* bk    = (const float*)d_in[4];
    const float* wv    = (const float*)d_in[5];
    const float* bv    = (const float*)d_in[6];
    const float* gamma = (const float*)d_in[7];
    const float* bnw   = (const float*)d_in[8];
    const float* bnb   = (const float*)d_in[9];
    float* out = (float*)d_out;

    dim3 gA(NPIX/128, 5, BATCH);
    projmma_kernel<<<gA, 256>>>(x, wq, bq, wk, bk, wv, bv);

    qkpack_kernel<<<(BATCH*32*NPIX/4)/256, 256>>>();

    cudaFuncSetAttribute(attn_kernel, cudaFuncAttributeMaxDynamicSharedMemorySize, ATTN_SMEM);
    attn_kernel<<<dim3(NQT, BATCH), 256, ATTN_SMEM>>>(x, gamma);

    bnstat_kernel<<<CCH, 256>>>(bnw, bnb);

    bnapply_kernel<<<(BATCH*CCH*NPIX)/(256*4), 256>>>(out);
}